// round 7
// baseline (speedup 1.0000x reference)
#include <cuda_runtime.h>
#include <math.h>

#define BB   64
#define STT  512
#define SLL  64
#define HH   256
#define NCC  20
#define NBLK 256   // blocks in each persistent kernel (must all be co-resident)

// ---------------- static device scratch (allocation-free) ----------------
__device__ float g_xw_tf[BB*STT*1024];   // precomputed x@Wih^T, text fwd
__device__ float g_xw_tb[BB*STT*1024];   // text bwd
__device__ float g_xw_lf[BB*SLL*1024];   // label fwd
__device__ float g_xw_lb[BB*SLL*1024];   // label bwd

__device__ float g_cpf[BB*STT*HH];       // ctx hidden sequences
__device__ float g_cpb[BB*STT*HH];
__device__ float g_chf[BB*SLL*HH];
__device__ float g_chb[BB*SLL*HH];
__device__ float g_mvp[BB*STT*2];
__device__ float g_mvh[BB*SLL*2];
__device__ float g_ah[4][2][BB*HH];      // agg hidden, parity double buffer
__device__ unsigned g_barc, g_finc, g_bara, g_fina;

__device__ __forceinline__ float sigf(float x) {
    return __fdividef(1.f, 1.f + __expf(-x));
}
__device__ __forceinline__ float tanhfast(float x) {
    return __fdividef(2.f, 1.f + __expf(-2.f * x)) - 1.f;
}

// Software grid barrier: monotonic counter; spin with short nanosleep backoff
// (tight spin without backoff risked wedging the memory system in R4).
__device__ __forceinline__ void gbar(unsigned* ctr, unsigned target) {
    __syncthreads();
    if (threadIdx.x == 0) {
        __threadfence();
        atomicAdd(ctr, 1u);
        while (*(volatile unsigned*)ctr < target) __nanosleep(20);
        __threadfence();
    }
    __syncthreads();
}
__device__ __forceinline__ void gbar_reset(unsigned* ctr, unsigned* fin) {
    __syncthreads();
    if (threadIdx.x == 0) {
        unsigned old = atomicAdd(fin, 1u);
        if (old == NBLK - 1) { *fin = 0u; *ctr = 0u; __threadfence(); }
    }
}

// ---------------------------------------------------------------------------
// Input projections: out[r, c] = sum_k emb[seq[r], k] * Wih[c, k]
// z: 0=text/fwd 1=text/bwd 2=label/fwd 3=label/bwd.
// 128x64 C-tile, 256 threads, 8x4 per thread, K chunks of 16.
// ---------------------------------------------------------------------------
__global__ __launch_bounds__(256) void xw_gemm(
    const int* __restrict__ text, const int* __restrict__ label,
    const float* __restrict__ emb,
    const float* __restrict__ Wih_f, const float* __restrict__ Wih_b)
{
    const int z = blockIdx.z;
    const int T = (z < 2) ? STT : SLL;
    const int r0 = blockIdx.y * 128;
    if (r0 >= BB * T) return;
    const int c0 = blockIdx.x * 64;
    const int* __restrict__ seq = (z < 2) ? text : label;
    const float* __restrict__ W = (z & 1) ? Wih_b : Wih_f;
    float* __restrict__ out = (z == 0) ? g_xw_tf : (z == 1) ? g_xw_tb
                            : (z == 2) ? g_xw_lf : g_xw_lb;

    __shared__ int   stok[128];
    __shared__ float sA[16][132];
    __shared__ float sB[16][68];
    const int tid = threadIdx.x;
    if (tid < 128) stok[tid] = seq[r0 + tid];
    __syncthreads();

    const int lrow = tid >> 1;          // 0..127
    const int lk8  = (tid & 1) * 8;     // 0 or 8
    const int lrb  = tid & 63;          // 0..63
    const int lkb4 = (tid >> 6) * 4;    // 0,4,8,12
    const float* __restrict__ arow = emb + stok[lrow] * 256 + lk8;
    const float* __restrict__ brow = W + (c0 + lrb) * 256 + lkb4;

    const int ty = tid >> 4, tx = tid & 15;
    float acc[8][4] = {};
    for (int k0 = 0; k0 < 256; k0 += 16) {
        float4 a0 = *(const float4*)(arow + k0);
        float4 a1 = *(const float4*)(arow + k0 + 4);
        float4 b0 = *(const float4*)(brow + k0);
        sA[lk8+0][lrow] = a0.x; sA[lk8+1][lrow] = a0.y;
        sA[lk8+2][lrow] = a0.z; sA[lk8+3][lrow] = a0.w;
        sA[lk8+4][lrow] = a1.x; sA[lk8+5][lrow] = a1.y;
        sA[lk8+6][lrow] = a1.z; sA[lk8+7][lrow] = a1.w;
        sB[lkb4+0][lrb] = b0.x; sB[lkb4+1][lrb] = b0.y;
        sB[lkb4+2][lrb] = b0.z; sB[lkb4+3][lrb] = b0.w;
        __syncthreads();
        #pragma unroll
        for (int k = 0; k < 16; k++) {
            float4 av0 = *(const float4*)&sA[k][ty * 8];
            float4 av1 = *(const float4*)&sA[k][ty * 8 + 4];
            float4 bv  = *(const float4*)&sB[k][tx * 4];
            const float a[8] = {av0.x, av0.y, av0.z, av0.w, av1.x, av1.y, av1.z, av1.w};
            #pragma unroll
            for (int i = 0; i < 8; i++) {
                acc[i][0] = fmaf(a[i], bv.x, acc[i][0]);
                acc[i][1] = fmaf(a[i], bv.y, acc[i][1]);
                acc[i][2] = fmaf(a[i], bv.z, acc[i][2]);
                acc[i][3] = fmaf(a[i], bv.w, acc[i][3]);
            }
        }
        __syncthreads();
    }
    #pragma unroll
    for (int i = 0; i < 8; i++) {
        const int r = r0 + ty * 8 + i;
        float4 v = make_float4(acc[i][0], acc[i][1], acc[i][2], acc[i][3]);
        *(float4*)&out[r * 1024 + c0 + tx * 4] = v;
    }
}

// ---------------------------------------------------------------------------
// Persistent context BiLSTM, batch-split: ONE grid barrier per step.
// 256 blocks x 256 threads, 2 blocks/SM (dyn smem 87KB, regs<=128).
// Blocks 0..127: text scans {fwd,bwd} x 16 unit-tiles x 4 batch-slices (16 b).
// Blocks 128..255: label scans, same decomposition; idle (barrier-only) t>=64.
// Each block: full K=256 recurrent GEMM for its (16u x 4g x 16b) gate tile,
// cell state in registers, h written to global hidden sequence.
// ---------------------------------------------------------------------------
__global__ __launch_bounds__(256, 2) void ctx_recurrent(
    const float* __restrict__ Whh_f, const float* __restrict__ Whh_b,
    const float* __restrict__ bih_f, const float* __restrict__ bhh_f,
    const float* __restrict__ bih_b, const float* __restrict__ bhh_b)
{
    extern __shared__ float smem[];
    float* sW = smem;              // [256][68]  (k-major, rows = u_local*4+g)
    float* sH = smem + 256 * 68;   // [256][17]  (k-major over units, 16 batches)

    const int tid = threadIdx.x;
    const int blk = blockIdx.x;
    const bool lab = blk >= 128;
    const int r = lab ? blk - 128 : blk;
    const int scan = (lab ? 2 : 0) + (r >> 6);
    const int utile = (r >> 2) & 15;
    const int bslice = r & 3;
    const int T = lab ? SLL : STT;
    const bool bwd = (r >> 6) & 1;
    float* __restrict__ hs = (scan == 0) ? g_cpf : (scan == 1) ? g_cpb
                           : (scan == 2) ? g_chf : g_chb;
    const float* __restrict__ xw = (scan == 0) ? g_xw_tf : (scan == 1) ? g_xw_tb
                                 : (scan == 2) ? g_xw_lf : g_xw_lb;
    const float* __restrict__ Whh  = bwd ? Whh_b : Whh_f;
    const float* __restrict__ bihp = bwd ? bih_b : bih_f;
    const float* __restrict__ bhhp = bwd ? bhh_b : bhh_f;

    const int bl   = tid & 15;
    const int b    = bslice * 16 + bl;
    const int ul   = tid >> 4;
    const int unit = utile * 16 + ul;

    float bias0 = bihp[0 * 256 + unit] + bhhp[0 * 256 + unit];
    float bias1 = bihp[1 * 256 + unit] + bhhp[1 * 256 + unit];
    float bias2 = bihp[2 * 256 + unit] + bhhp[2 * 256 + unit];
    float bias3 = bihp[3 * 256 + unit] + bhhp[3 * 256 + unit];

    // preload Whh tile once (persistent across all steps)
    for (int e = tid; e < 256 * 64; e += 256) {
        const int k = e >> 6, row = e & 63;
        const int grow = (row & 3) * 256 + utile * 16 + (row >> 2);
        sW[k * 68 + row] = Whh[grow * 256 + k];
    }

    const float* wbase = sW + ul * 4;
    float cell = 0.f;
    unsigned nb = 0;

    for (int t = 0; t < STT; t++) {
        const bool active = (!lab) || (t < SLL);
        if (active) {
            const int pos = bwd ? (T - 1 - t) : t;
            float a0 = 0.f, a1 = 0.f, a2 = 0.f, a3 = 0.f;
            if (t > 0) {
                const int prevpos = bwd ? pos + 1 : pos - 1;
                {   // fill sH[u][b] for all 256 units of own 16 batches
                    const int fb  = tid & 15;
                    const int fu0 = (tid >> 4) * 16;
                    const float4* src = (const float4*)
                        &hs[((bslice * 16 + fb) * T + prevpos) * HH + fu0];
                    float4 v0 = src[0], v1 = src[1], v2 = src[2], v3 = src[3];
                    float* d = sH + fu0 * 17 + fb;
                    d[0*17]=v0.x;  d[1*17]=v0.y;  d[2*17]=v0.z;  d[3*17]=v0.w;
                    d[4*17]=v1.x;  d[5*17]=v1.y;  d[6*17]=v1.z;  d[7*17]=v1.w;
                    d[8*17]=v2.x;  d[9*17]=v2.y;  d[10*17]=v2.z; d[11*17]=v2.w;
                    d[12*17]=v3.x; d[13*17]=v3.y; d[14*17]=v3.z; d[15*17]=v3.w;
                }
                __syncthreads();
                #pragma unroll 8
                for (int k = 0; k < 256; k++) {
                    const float h = sH[k * 17 + bl];
                    const float4 w = *(const float4*)(wbase + k * 68);
                    a0 = fmaf(h, w.x, a0);
                    a1 = fmaf(h, w.y, a1);
                    a2 = fmaf(h, w.z, a2);
                    a3 = fmaf(h, w.w, a3);
                }
            }
            const float* xp = xw + (b * T + pos) * 1024 + unit;
            const float gi = sigf(a0 + bias0 + xp[0]);
            const float gf = sigf(a1 + bias1 + xp[256]);
            const float gg = tanhfast(a2 + bias2 + xp[512]);
            const float go = sigf(a3 + bias3 + xp[768]);
            cell = (t == 0 ? 0.f : cell * gf) + gi * gg;
            hs[(b * T + pos) * HH + unit] = go * tanhfast(cell);
        }
        nb++; gbar(&g_barc, nb * NBLK);
    }
    gbar_reset(&g_barc, &g_finc);
}

// ---------------------------------------------------------------------------
// Multi-perspective matching (L=1): one warp per (b,t), both perspectives.
// ---------------------------------------------------------------------------
__global__ void match_kernel(const float* __restrict__ w1,
                             const float* __restrict__ w2)
{
    const int wid  = (blockIdx.x * blockDim.x + threadIdx.x) >> 5;
    const int lane = threadIdx.x & 31;
    const float *v1a, *v2a, *v1b, *v2b;
    float* out;
    if (wid < BB * STT) {
        const int b = wid / STT, t = wid % STT;
        v1a = g_cpf + (b * STT + t) * HH;
        v2a = g_chf + (b * SLL + (SLL - 1)) * HH;
        v1b = g_cpb + (b * STT + t) * HH;
        v2b = g_chb + (b * SLL + 0) * HH;
        out = g_mvp + (b * STT + t) * 2;
    } else {
        const int id = wid - BB * STT;
        if (id >= BB * SLL) return;
        const int b = id / SLL, t = id % SLL;
        v1a = g_chf + (b * SLL + t) * HH;
        v2a = g_cpf + (b * STT + (STT - 1)) * HH;
        v1b = g_chb + (b * SLL + t) * HH;
        v2b = g_cpb + (b * STT + 0) * HH;
        out = g_mvh + (b * SLL + t) * 2;
    }
    float num = 0.f, s1 = 0.f, s2 = 0.f;
    for (int k = lane; k < HH; k += 32) {
        const float w = w1[k];
        const float a = w * v1a[k];
        const float c = w * v2a[k];
        num += a * c; s1 += a * a; s2 += c * c;
    }
    #pragma unroll
    for (int o = 16; o > 0; o >>= 1) {
        num += __shfl_xor_sync(0xffffffff, num, o);
        s1  += __shfl_xor_sync(0xffffffff, s1,  o);
        s2  += __shfl_xor_sync(0xffffffff, s2,  o);
    }
    if (lane == 0) out[0] = num / fmaxf(sqrtf(s1) * sqrtf(s2), 1e-8f);
    num = 0.f; s1 = 0.f; s2 = 0.f;
    for (int k = lane; k < HH; k += 32) {
        const float w = w2[k];
        const float a = w * v1b[k];
        const float c = w * v2b[k];
        num += a * c; s1 += a * a; s2 += c * c;
    }
    #pragma unroll
    for (int o = 16; o > 0; o >>= 1) {
        num += __shfl_xor_sync(0xffffffff, num, o);
        s1  += __shfl_xor_sync(0xffffffff, s1,  o);
        s2  += __shfl_xor_sync(0xffffffff, s2,  o);
    }
    if (lane == 0) out[1] = num / fmaxf(sqrtf(s1) * sqrtf(s2), 1e-8f);
}

// ---------------------------------------------------------------------------
// Persistent aggregation BiLSTM, batch-split, one barrier per step.
// Blocks 0..127: premise scans {fwd,bwd} (T=512, mv=g_mvp).
// Blocks 128..255: hypothesis scans (T=64, mv=g_mvh), idle t>=64.
// Input dim 2 folded into the gate epilogue. Hidden in parity-rotated
// global buffers; both T are even -> final state lands in parity 0.
// ---------------------------------------------------------------------------
__global__ __launch_bounds__(256, 2) void agg_recurrent(
    const float* __restrict__ Wih_f, const float* __restrict__ Whh_f,
    const float* __restrict__ bih_f, const float* __restrict__ bhh_f,
    const float* __restrict__ Wih_b, const float* __restrict__ Whh_b,
    const float* __restrict__ bih_b, const float* __restrict__ bhh_b)
{
    extern __shared__ float smem[];
    float* sW = smem;
    float* sH = smem + 256 * 68;

    const int tid = threadIdx.x;
    const int blk = blockIdx.x;
    const bool lab = blk >= 128;
    const int r = lab ? blk - 128 : blk;
    const int scan = (lab ? 2 : 0) + (r >> 6);
    const int utile = (r >> 2) & 15;
    const int bslice = r & 3;
    const int T = lab ? SLL : STT;
    const bool bwd = (r >> 6) & 1;
    const float* __restrict__ mv   = lab ? g_mvh : g_mvp;
    const float* __restrict__ Whh  = bwd ? Whh_b : Whh_f;
    const float* __restrict__ Wih  = bwd ? Wih_b : Wih_f;
    const float* __restrict__ bihp = bwd ? bih_b : bih_f;
    const float* __restrict__ bhhp = bwd ? bhh_b : bhh_f;

    const int bl   = tid & 15;
    const int b    = bslice * 16 + bl;
    const int ul   = tid >> 4;
    const int unit = utile * 16 + ul;

    float bias[4], wx0[4], wx1[4];
    #pragma unroll
    for (int g = 0; g < 4; g++) {
        const int grow = g * 256 + unit;
        bias[g] = bihp[grow] + bhhp[grow];
        wx0[g]  = Wih[grow * 2 + 0];
        wx1[g]  = Wih[grow * 2 + 1];
    }

    for (int e = tid; e < 256 * 64; e += 256) {
        const int k = e >> 6, row = e & 63;
        const int grow = (row & 3) * 256 + utile * 16 + (row >> 2);
        sW[k * 68 + row] = Whh[grow * 256 + k];
    }

    const float* wbase = sW + ul * 4;
    float cell = 0.f;
    unsigned nb = 0;

    for (int t = 0; t < STT; t++) {
        const bool active = (!lab) || (t < SLL);
        if (active) {
            const int pos = bwd ? (T - 1 - t) : t;
            float a0 = 0.f, a1 = 0.f, a2 = 0.f, a3 = 0.f;
            if (t > 0) {
                const float* __restrict__ hprev = g_ah[scan][t & 1];
                {
                    const int fb  = tid & 15;
                    const int fu0 = (tid >> 4) * 16;
                    const float4* src = (const float4*)
                        &hprev[(bslice * 16 + fb) * HH + fu0];
                    float4 v0 = src[0], v1 = src[1], v2 = src[2], v3 = src[3];
                    float* d = sH + fu0 * 17 + fb;
                    d[0*17]=v0.x;  d[1*17]=v0.y;  d[2*17]=v0.z;  d[3*17]=v0.w;
                    d[4*17]=v1.x;  d[5*17]=v1.y;  d[6*17]=v1.z;  d[7*17]=v1.w;
                    d[8*17]=v2.x;  d[9*17]=v2.y;  d[10*17]=v2.z; d[11*17]=v2.w;
                    d[12*17]=v3.x; d[13*17]=v3.y; d[14*17]=v3.z; d[15*17]=v3.w;
                }
                __syncthreads();
                #pragma unroll 8
                for (int k = 0; k < 256; k++) {
                    const float h = sH[k * 17 + bl];
                    const float4 w = *(const float4*)(wbase + k * 68);
                    a0 = fmaf(h, w.x, a0);
                    a1 = fmaf(h, w.y, a1);
                    a2 = fmaf(h, w.z, a2);
                    a3 = fmaf(h, w.w, a3);
                }
            }
            const float m0 = mv[(b * T + pos) * 2 + 0];
            const float m1 = mv[(b * T + pos) * 2 + 1];
            const float gi = sigf(a0 + bias[0] + wx0[0] * m0 + wx1[0] * m1);
            const float gf = sigf(a1 + bias[1] + wx0[1] * m0 + wx1[1] * m1);
            const float gg = tanhfast(a2 + bias[2] + wx0[2] * m0 + wx1[2] * m1);
            const float go = sigf(a3 + bias[3] + wx0[3] * m0 + wx1[3] * m1);
            cell = (t == 0 ? 0.f : cell * gf) + gi * gg;
            g_ah[scan][(t + 1) & 1][b * HH + unit] = go * tanhfast(cell);
        }
        nb++; gbar(&g_bara, nb * NBLK);
    }
    gbar_reset(&g_bara, &g_fina);
}

// ---------------------------------------------------------------------------
// Final head: x = [pT_f, pT_b, hT_f, hT_b] (64 x 1024) -> tanh(fc1) -> fc2.
// ---------------------------------------------------------------------------
__global__ __launch_bounds__(256) void fc_kernel(
    const float* __restrict__ fc1_W, const float* __restrict__ fc1_b,
    const float* __restrict__ fc2_W, const float* __restrict__ fc2_b,
    float* __restrict__ out)
{
    const int b = blockIdx.x;
    const int tid = threadIdx.x;
    __shared__ float sx[1024];
    __shared__ float sy[512];
    #pragma unroll
    for (int q = 0; q < 4; q++) {
        const int j = tid + q * 256;
        sx[j] = g_ah[j >> 8][0][b * HH + (j & 255)];
    }
    __syncthreads();
    #pragma unroll
    for (int q = 0; q < 2; q++) {
        const int r = tid + q * 256;
        float acc = fc1_b[r];
        const float* wr = fc1_W + r * 1024;
        #pragma unroll 8
        for (int k = 0; k < 1024; k++) acc = fmaf(wr[k], sx[k], acc);
        sy[r] = tanhf(acc);
    }
    __syncthreads();
    if (tid < NCC) {
        float acc = fc2_b[tid];
        const float* wr = fc2_W + tid * 512;
        #pragma unroll 8
        for (int k = 0; k < 512; k++) acc = fmaf(wr[k], sy[k], acc);
        out[b * NCC + tid] = acc;
    }
}

// ---------------------------------------------------------------------------
extern "C" void kernel_launch(void* const* d_in, const int* in_sizes, int n_in,
                              void* d_out, int out_size)
{
    const int*   text       = (const int*)  d_in[0];
    const int*   label      = (const int*)  d_in[1];
    const float* emb        = (const float*)d_in[2];
    const float* ctx_Wih_f  = (const float*)d_in[3];
    const float* ctx_Whh_f  = (const float*)d_in[4];
    const float* ctx_bih_f  = (const float*)d_in[5];
    const float* ctx_bhh_f  = (const float*)d_in[6];
    const float* ctx_Wih_b  = (const float*)d_in[7];
    const float* ctx_Whh_b  = (const float*)d_in[8];
    const float* ctx_bih_b  = (const float*)d_in[9];
    const float* ctx_bhh_b  = (const float*)d_in[10];
    const float* mp_w1      = (const float*)d_in[11];
    const float* mp_w2      = (const float*)d_in[12];
    const float* agg_Wih_f  = (const float*)d_in[13];
    const float* agg_Whh_f  = (const float*)d_in[14];
    const float* agg_bih_f  = (const float*)d_in[15];
    const float* agg_bhh_f  = (const float*)d_in[16];
    const float* agg_Wih_b  = (const float*)d_in[17];
    const float* agg_Whh_b  = (const float*)d_in[18];
    const float* agg_bih_b  = (const float*)d_in[19];
    const float* agg_bhh_b  = (const float*)d_in[20];
    const float* fc1_W      = (const float*)d_in[21];
    const float* fc1_b      = (const float*)d_in[22];
    const float* fc2_W      = (const float*)d_in[23];
    const float* fc2_b      = (const float*)d_in[24];
    float* out = (float*)d_out;

    const int SMEM_REC = (256 * 68 + 256 * 17) * 4;  // 87040 B dynamic smem
    cudaFuncSetAttribute(ctx_recurrent,
                         cudaFuncAttributeMaxDynamicSharedMemorySize, SMEM_REC);
    cudaFuncSetAttribute(agg_recurrent,
                         cudaFuncAttributeMaxDynamicSharedMemorySize, SMEM_REC);

    // 1. input projections (bulk GEMM over all timesteps)
    xw_gemm<<<dim3(16, 256, 4), 256>>>(text, label, emb, ctx_Wih_f, ctx_Wih_b);
    // 2. context BiLSTM (persistent, 1 grid barrier per step)
    ctx_recurrent<<<NBLK, 256, SMEM_REC>>>(ctx_Whh_f, ctx_Whh_b,
        ctx_bih_f, ctx_bhh_f, ctx_bih_b, ctx_bhh_b);
    // 3. matching
    const int npairs = BB * STT + BB * SLL;
    match_kernel<<<(npairs + 7) / 8, 256>>>(mp_w1, mp_w2);
    // 4. aggregation BiLSTM (persistent)
    agg_recurrent<<<NBLK, 256, SMEM_REC>>>(agg_Wih_f, agg_Whh_f,
        agg_bih_f, agg_bhh_f, agg_Wih_b, agg_Whh_b, agg_bih_b, agg_bhh_b);
    // 5. FC head
    fc_kernel<<<BB, 256>>>(fc1_W, fc1_b, fc2_W, fc2_b, out);
}